// round 4
// baseline (speedup 1.0000x reference)
#include <cuda_runtime.h>
#include <math.h>

#define BQ   4096
#define NEX  16384
#define DIN  1024
#define DF   256
#define NLAB 28
#define DC   64
#define SPLITS 8
#define KEYS_PER (NEX/SPLITS)   // 2048

// Scratch (device globals: allocation-free rule)
__device__ float g_Q[(size_t)BQ*DF];     // l2-normalized projected queries
__device__ float g_K[(size_t)NEX*DF];    // l2-normalized projected exemplars
__device__ float g_V[(size_t)NEX*DC];    // exemplar class reps
__device__ float g_num[(size_t)BQ*DC];   // echo numerator
__device__ float g_den[BQ];              // sum |s^3|

// ---------------------------------------------------------------------------
__global__ void zero_kernel(float* out0){
    int i = blockIdx.x*blockDim.x + threadIdx.x;
    int st = gridDim.x*blockDim.x;
    for (int j=i; j<BQ*DC; j+=st) g_num[j] = 0.f;
    for (int j=i; j<BQ;    j+=st) g_den[j] = 0.f;
    if (blockIdx.x==0 && threadIdx.x==0) out0[0] = 0.f;
}

// ---------------------------------------------------------------------------
// C[m][n] = sum_k A[m][k]*B[n][k]   (NT GEMM, both K-major)
// 64x64 tile, BK=16, 16x16 threads, 4x4 fragments
__global__ __launch_bounds__(256) void gemm_nt64(
    const float* __restrict__ A, const float* __restrict__ Bm,
    float* __restrict__ C, int M, int N, int K)
{
    __shared__ float As[16][64];
    __shared__ float Bs[16][64];
    const int tx = threadIdx.x, ty = threadIdx.y;
    const int tid = ty*16 + tx;
    const int m0 = blockIdx.x*64, n0 = blockIdx.y*64;
    const int lrow = tid >> 2;          // 0..63
    const int lk4  = (tid & 3) << 2;    // 0,4,8,12
    const float* Ap = A  + (size_t)(m0+lrow)*K + lk4;
    const float* Bp = Bm + (size_t)(n0+lrow)*K + lk4;
    float acc[4][4] = {};
    for (int kc = 0; kc < K; kc += 16){
        float4 av = *(const float4*)(Ap + kc);
        float4 bv = *(const float4*)(Bp + kc);
        As[lk4+0][lrow]=av.x; As[lk4+1][lrow]=av.y; As[lk4+2][lrow]=av.z; As[lk4+3][lrow]=av.w;
        Bs[lk4+0][lrow]=bv.x; Bs[lk4+1][lrow]=bv.y; Bs[lk4+2][lrow]=bv.z; Bs[lk4+3][lrow]=bv.w;
        __syncthreads();
        #pragma unroll
        for (int k = 0; k < 16; k++){
            float4 aq = *(const float4*)&As[k][ty<<2];
            float4 bq = *(const float4*)&Bs[k][tx<<2];
            float am[4] = {aq.x, aq.y, aq.z, aq.w};
            float bn[4] = {bq.x, bq.y, bq.z, bq.w};
            #pragma unroll
            for (int i = 0; i < 4; i++)
                #pragma unroll
                for (int j = 0; j < 4; j++)
                    acc[i][j] += am[i]*bn[j];
        }
        __syncthreads();
    }
    #pragma unroll
    for (int i = 0; i < 4; i++){
        float4 v = {acc[i][0], acc[i][1], acc[i][2], acc[i][3]};
        *(float4*)(C + (size_t)(m0 + ty*4 + i)*N + n0 + tx*4) = v;
    }
}

// ---------------------------------------------------------------------------
// In-place L2 row normalize, width DF=256, 64 threads/row
__global__ void l2norm_kernel(float* __restrict__ X){
    __shared__ float ws[2];
    const int r = blockIdx.x, t = threadIdx.x;
    float4* row = (float4*)(X + (size_t)r*DF);
    float4 v = row[t];
    float ss = v.x*v.x + v.y*v.y + v.z*v.z + v.w*v.w;
    #pragma unroll
    for (int o = 16; o > 0; o >>= 1) ss += __shfl_down_sync(0xffffffffu, ss, o);
    if ((t & 31) == 0) ws[t>>5] = ss;
    __syncthreads();
    float inv = 1.f / fmaxf(sqrtf(ws[0] + ws[1]), 1e-12f);
    v.x *= inv; v.y *= inv; v.z *= inv; v.w *= inv;
    row[t] = v;
}

// ---------------------------------------------------------------------------
// g_V[r] = l1norm(ex_classes[r]) @ class_reps   (one block per row, 64 thr)
__global__ void exrep_kernel(const float* __restrict__ exc,
                             const float* __restrict__ creps){
    __shared__ float cs[NLAB*DC];
    __shared__ float rowv[NLAB];
    const int r = blockIdx.x, t = threadIdx.x;
    for (int i = t; i < NLAB*DC; i += 64) cs[i] = creps[i];
    if (t < NLAB) rowv[t] = exc[(size_t)r*NLAB + t];
    __syncthreads();
    float s = 0.f;
    #pragma unroll
    for (int k = 0; k < NLAB; k++) s += fabsf(rowv[k]);
    float inv = 1.f / fmaxf(s, 1e-12f);
    float acc = 0.f;
    #pragma unroll
    for (int k = 0; k < NLAB; k++) acc += rowv[k]*cs[k*DC + t];
    g_V[(size_t)r*DC + t] = acc*inv;
}

// ---------------------------------------------------------------------------
// Fused: S = Qblk @ K^T tile, a = s^3, num += a @ V, den += sum|a|
// grid = (BQ/64, SPLITS), 16x16 threads
__global__ __launch_bounds__(256) void attn_kernel(){
    __shared__ float As[16][64];
    __shared__ float Bs[16][64];
    __shared__ float Ps[64][65];   // padded: conflict-free column reads
    __shared__ float Vs[64][64];
    const int tx = threadIdx.x, ty = threadIdx.y;
    const int tid = ty*16 + tx;
    const int q0 = blockIdx.x*64;
    const int kb = blockIdx.y*KEYS_PER;
    const int lrow = tid >> 2, lk4 = (tid & 3) << 2;
    const float* Qp = g_Q + (size_t)(q0+lrow)*DF + lk4;
    float num[4][4] = {};
    float den[4] = {};
    for (int kt = 0; kt < KEYS_PER; kt += 64){
        const int n0 = kb + kt;
        const float* Kp = g_K + (size_t)(n0+lrow)*DF + lk4;
        float sacc[4][4] = {};
        for (int kc = 0; kc < DF; kc += 16){
            float4 av = *(const float4*)(Qp + kc);
            float4 bv = *(const float4*)(Kp + kc);
            As[lk4+0][lrow]=av.x; As[lk4+1][lrow]=av.y; As[lk4+2][lrow]=av.z; As[lk4+3][lrow]=av.w;
            Bs[lk4+0][lrow]=bv.x; Bs[lk4+1][lrow]=bv.y; Bs[lk4+2][lrow]=bv.z; Bs[lk4+3][lrow]=bv.w;
            __syncthreads();
            #pragma unroll
            for (int k = 0; k < 16; k++){
                float4 aq = *(const float4*)&As[k][ty<<2];
                float4 bq = *(const float4*)&Bs[k][tx<<2];
                float am[4] = {aq.x, aq.y, aq.z, aq.w};
                float bn[4] = {bq.x, bq.y, bq.z, bq.w};
                #pragma unroll
                for (int i = 0; i < 4; i++)
                    #pragma unroll
                    for (int j = 0; j < 4; j++)
                        sacc[i][j] += am[i]*bn[j];
            }
            __syncthreads();
        }
        // load V tile (64 keys x 64 dims)
        {
            const int vc  = (tid & 15) << 2;
            const int vr0 = tid >> 4;
            #pragma unroll
            for (int rr = 0; rr < 4; rr++){
                int vr = vr0 + rr*16;
                *(float4*)&Vs[vr][vc] = *(const float4*)&g_V[(size_t)(n0+vr)*DC + vc];
            }
        }
        // transform: a = s^3  (== sign(s)*|s|^3); store P, accumulate den
        #pragma unroll
        for (int i = 0; i < 4; i++)
            #pragma unroll
            for (int j = 0; j < 4; j++){
                float s = sacc[i][j];
                float a = s*s*s;
                den[i] += fabsf(a);
                Ps[ty*4 + i][tx*4 + j] = a;
            }
        __syncthreads();
        // PV: num[m][d] += P[m][n] * V[n][d]
        #pragma unroll 4
        for (int n = 0; n < 64; n++){
            float4 vv = *(const float4*)&Vs[n][tx<<2];
            float p0 = Ps[ty*4+0][n], p1 = Ps[ty*4+1][n];
            float p2 = Ps[ty*4+2][n], p3 = Ps[ty*4+3][n];
            num[0][0]+=p0*vv.x; num[0][1]+=p0*vv.y; num[0][2]+=p0*vv.z; num[0][3]+=p0*vv.w;
            num[1][0]+=p1*vv.x; num[1][1]+=p1*vv.y; num[1][2]+=p1*vv.z; num[1][3]+=p1*vv.w;
            num[2][0]+=p2*vv.x; num[2][1]+=p2*vv.y; num[2][2]+=p2*vv.z; num[2][3]+=p2*vv.w;
            num[3][0]+=p3*vv.x; num[3][1]+=p3*vv.y; num[3][2]+=p3*vv.z; num[3][3]+=p3*vv.w;
        }
        __syncthreads();
    }
    // den: reduce across tx (16 lanes per half-warp), then 1 atomic
    #pragma unroll
    for (int i = 0; i < 4; i++){
        float d = den[i];
        #pragma unroll
        for (int o = 8; o > 0; o >>= 1) d += __shfl_down_sync(0xffffffffu, d, o, 16);
        if (tx == 0) atomicAdd(&g_den[q0 + ty*4 + i], d);
    }
    // num: each thread owns distinct elements; SPLITS-way contention only
    #pragma unroll
    for (int i = 0; i < 4; i++)
        #pragma unroll
        for (int j = 0; j < 4; j++)
            atomicAdd(&g_num[(size_t)(q0 + ty*4 + i)*DC + tx*4 + j], num[i][j]);
}

// ---------------------------------------------------------------------------
// echo = num/max(den,eps); neg_dists = -||echo - class_reps||; BCE mean
// one block (32 threads) per query row
__global__ void loss_kernel(const float* __restrict__ labels,
                            const float* __restrict__ creps,
                            float* __restrict__ out){
    __shared__ float echo_s[DC];
    const int b = blockIdx.x, t = threadIdx.x;
    float inv = 1.f / fmaxf(g_den[b], 1e-12f);
    echo_s[t]      = g_num[(size_t)b*DC + t]      * inv;
    echo_s[t + 32] = g_num[(size_t)b*DC + t + 32] * inv;
    __syncwarp();
    float le = 0.f;
    if (t < NLAB){
        float ss = 0.f;
        #pragma unroll
        for (int d = 0; d < DC; d++){
            float df = echo_s[d] - creps[t*DC + d];
            ss += df*df;
        }
        float x = -sqrtf(ss);                 // neg dist (<= 0)
        out[1 + (size_t)b*NLAB + t] = x;
        float y = labels[(size_t)b*NLAB + t];
        // BCEWithLogits elem: log1p(exp(x)) - y*x   (valid for x<=0)
        le = log1pf(expf(x)) - y*x;
    }
    #pragma unroll
    for (int o = 16; o > 0; o >>= 1) le += __shfl_down_sync(0xffffffffu, le, o);
    if (t == 0) atomicAdd(out, le * (1.f/((float)BQ*(float)NLAB)));
}

// ---------------------------------------------------------------------------
extern "C" void kernel_launch(void* const* d_in, const int* in_sizes, int n_in,
                              void* d_out, int out_size){
    const float* features    = (const float*)d_in[0];
    const float* labels      = (const float*)d_in[1];
    const float* ex_features = (const float*)d_in[2];
    const float* ex_classes  = (const float*)d_in[3];
    const float* g_w         = (const float*)d_in[4];
    const float* class_reps  = (const float*)d_in[5];
    float* out = (float*)d_out;

    float *pQ, *pK;
    cudaGetSymbolAddress((void**)&pQ, g_Q);
    cudaGetSymbolAddress((void**)&pK, g_K);

    zero_kernel<<<1024, 256>>>(out);

    dim3 blk(16, 16);
    gemm_nt64<<<dim3(BQ/64,  DF/64), blk>>>(features,    g_w, pQ, BQ,  DF, DIN);
    gemm_nt64<<<dim3(NEX/64, DF/64), blk>>>(ex_features, g_w, pK, NEX, DF, DIN);
    l2norm_kernel<<<BQ,  64>>>(pQ);
    l2norm_kernel<<<NEX, 64>>>(pK);
    exrep_kernel<<<NEX, 64>>>(ex_classes, class_reps);
    attn_kernel<<<dim3(BQ/64, SPLITS), blk>>>();
    loss_kernel<<<BQ, 32>>>(labels, class_reps, out);
}

// round 5
// speedup vs baseline: 1.0010x; 1.0010x over previous
#include <cuda_runtime.h>
#include <math.h>

#define BQ   4096
#define NEX  16384
#define DIN  1024
#define DF   256
#define NLAB 28
#define DC   64
#define SPLITS 8
#define KEYS_PER (NEX/SPLITS)   // 2048

// Scratch (device globals: allocation-free rule)
__device__ float g_Q[(size_t)BQ*DF];     // l2-normalized projected queries
__device__ float g_K[(size_t)NEX*DF];    // l2-normalized projected exemplars
__device__ float g_V[(size_t)NEX*DC];    // exemplar class reps
__device__ float g_num[(size_t)BQ*DC];   // echo numerator
__device__ float g_den[BQ];              // sum |s^3|

// ---------------------------------------------------------------------------
__global__ void zero_kernel(float* out0){
    int i = blockIdx.x*blockDim.x + threadIdx.x;
    int st = gridDim.x*blockDim.x;
    for (int j=i; j<BQ*DC; j+=st) g_num[j] = 0.f;
    for (int j=i; j<BQ;    j+=st) g_den[j] = 0.f;
    if (blockIdx.x==0 && threadIdx.x==0) out0[0] = 0.f;
}

// ---------------------------------------------------------------------------
// C[m][n] = sum_k A[m][k]*B[n][k]   (NT GEMM, both K-major)
// 64x64 tile, BK=16, 16x16 threads, 4x4 fragments
__global__ __launch_bounds__(256) void gemm_nt64(
    const float* __restrict__ A, const float* __restrict__ Bm,
    float* __restrict__ C, int M, int N, int K)
{
    __shared__ float As[16][64];
    __shared__ float Bs[16][64];
    const int tx = threadIdx.x, ty = threadIdx.y;
    const int tid = ty*16 + tx;
    const int m0 = blockIdx.x*64, n0 = blockIdx.y*64;
    const int lrow = tid >> 2;          // 0..63
    const int lk4  = (tid & 3) << 2;    // 0,4,8,12
    const float* Ap = A  + (size_t)(m0+lrow)*K + lk4;
    const float* Bp = Bm + (size_t)(n0+lrow)*K + lk4;
    float acc[4][4] = {};
    for (int kc = 0; kc < K; kc += 16){
        float4 av = *(const float4*)(Ap + kc);
        float4 bv = *(const float4*)(Bp + kc);
        As[lk4+0][lrow]=av.x; As[lk4+1][lrow]=av.y; As[lk4+2][lrow]=av.z; As[lk4+3][lrow]=av.w;
        Bs[lk4+0][lrow]=bv.x; Bs[lk4+1][lrow]=bv.y; Bs[lk4+2][lrow]=bv.z; Bs[lk4+3][lrow]=bv.w;
        __syncthreads();
        #pragma unroll
        for (int k = 0; k < 16; k++){
            float4 aq = *(const float4*)&As[k][ty<<2];
            float4 bq = *(const float4*)&Bs[k][tx<<2];
            float am[4] = {aq.x, aq.y, aq.z, aq.w};
            float bn[4] = {bq.x, bq.y, bq.z, bq.w};
            #pragma unroll
            for (int i = 0; i < 4; i++)
                #pragma unroll
                for (int j = 0; j < 4; j++)
                    acc[i][j] += am[i]*bn[j];
        }
        __syncthreads();
    }
    #pragma unroll
    for (int i = 0; i < 4; i++){
        float4 v = {acc[i][0], acc[i][1], acc[i][2], acc[i][3]};
        *(float4*)(C + (size_t)(m0 + ty*4 + i)*N + n0 + tx*4) = v;
    }
}

// ---------------------------------------------------------------------------
// In-place L2 row normalize, width DF=256, 64 threads/row
__global__ void l2norm_kernel(float* __restrict__ X){
    __shared__ float ws[2];
    const int r = blockIdx.x, t = threadIdx.x;
    float4* row = (float4*)(X + (size_t)r*DF);
    float4 v = row[t];
    float ss = v.x*v.x + v.y*v.y + v.z*v.z + v.w*v.w;
    #pragma unroll
    for (int o = 16; o > 0; o >>= 1) ss += __shfl_down_sync(0xffffffffu, ss, o);
    if ((t & 31) == 0) ws[t>>5] = ss;
    __syncthreads();
    float inv = 1.f / fmaxf(sqrtf(ws[0] + ws[1]), 1e-12f);
    v.x *= inv; v.y *= inv; v.z *= inv; v.w *= inv;
    row[t] = v;
}

// ---------------------------------------------------------------------------
// g_V[r] = l1norm(ex_classes[r]) @ class_reps   (one block per row, 64 thr)
__global__ void exrep_kernel(const float* __restrict__ exc,
                             const float* __restrict__ creps){
    __shared__ float cs[NLAB*DC];
    __shared__ float rowv[NLAB];
    const int r = blockIdx.x, t = threadIdx.x;
    for (int i = t; i < NLAB*DC; i += 64) cs[i] = creps[i];
    if (t < NLAB) rowv[t] = exc[(size_t)r*NLAB + t];
    __syncthreads();
    float s = 0.f;
    #pragma unroll
    for (int k = 0; k < NLAB; k++) s += fabsf(rowv[k]);
    float inv = 1.f / fmaxf(s, 1e-12f);
    float acc = 0.f;
    #pragma unroll
    for (int k = 0; k < NLAB; k++) acc += rowv[k]*cs[k*DC + t];
    g_V[(size_t)r*DC + t] = acc*inv;
}

// ---------------------------------------------------------------------------
// Fused: S = Qblk @ K^T tile, a = s^3, num += a @ V, den += sum|a|
// grid = (BQ/64, SPLITS), 16x16 threads
__global__ __launch_bounds__(256) void attn_kernel(){
    __shared__ float As[16][64];
    __shared__ float Bs[16][64];
    __shared__ float Ps[64][65];   // padded: conflict-free column reads
    __shared__ float Vs[64][64];
    const int tx = threadIdx.x, ty = threadIdx.y;
    const int tid = ty*16 + tx;
    const int q0 = blockIdx.x*64;
    const int kb = blockIdx.y*KEYS_PER;
    const int lrow = tid >> 2, lk4 = (tid & 3) << 2;
    const float* Qp = g_Q + (size_t)(q0+lrow)*DF + lk4;
    float num[4][4] = {};
    float den[4] = {};
    for (int kt = 0; kt < KEYS_PER; kt += 64){
        const int n0 = kb + kt;
        const float* Kp = g_K + (size_t)(n0+lrow)*DF + lk4;
        float sacc[4][4] = {};
        for (int kc = 0; kc < DF; kc += 16){
            float4 av = *(const float4*)(Qp + kc);
            float4 bv = *(const float4*)(Kp + kc);
            As[lk4+0][lrow]=av.x; As[lk4+1][lrow]=av.y; As[lk4+2][lrow]=av.z; As[lk4+3][lrow]=av.w;
            Bs[lk4+0][lrow]=bv.x; Bs[lk4+1][lrow]=bv.y; Bs[lk4+2][lrow]=bv.z; Bs[lk4+3][lrow]=bv.w;
            __syncthreads();
            #pragma unroll
            for (int k = 0; k < 16; k++){
                float4 aq = *(const float4*)&As[k][ty<<2];
                float4 bq = *(const float4*)&Bs[k][tx<<2];
                float am[4] = {aq.x, aq.y, aq.z, aq.w};
                float bn[4] = {bq.x, bq.y, bq.z, bq.w};
                #pragma unroll
                for (int i = 0; i < 4; i++)
                    #pragma unroll
                    for (int j = 0; j < 4; j++)
                        sacc[i][j] += am[i]*bn[j];
            }
            __syncthreads();
        }
        // load V tile (64 keys x 64 dims)
        {
            const int vc  = (tid & 15) << 2;
            const int vr0 = tid >> 4;
            #pragma unroll
            for (int rr = 0; rr < 4; rr++){
                int vr = vr0 + rr*16;
                *(float4*)&Vs[vr][vc] = *(const float4*)&g_V[(size_t)(n0+vr)*DC + vc];
            }
        }
        // transform: a = s^3  (== sign(s)*|s|^3); store P, accumulate den
        #pragma unroll
        for (int i = 0; i < 4; i++)
            #pragma unroll
            for (int j = 0; j < 4; j++){
                float s = sacc[i][j];
                float a = s*s*s;
                den[i] += fabsf(a);
                Ps[ty*4 + i][tx*4 + j] = a;
            }
        __syncthreads();
        // PV: num[m][d] += P[m][n] * V[n][d]
        #pragma unroll 4
        for (int n = 0; n < 64; n++){
            float4 vv = *(const float4*)&Vs[n][tx<<2];
            float p0 = Ps[ty*4+0][n], p1 = Ps[ty*4+1][n];
            float p2 = Ps[ty*4+2][n], p3 = Ps[ty*4+3][n];
            num[0][0]+=p0*vv.x; num[0][1]+=p0*vv.y; num[0][2]+=p0*vv.z; num[0][3]+=p0*vv.w;
            num[1][0]+=p1*vv.x; num[1][1]+=p1*vv.y; num[1][2]+=p1*vv.z; num[1][3]+=p1*vv.w;
            num[2][0]+=p2*vv.x; num[2][1]+=p2*vv.y; num[2][2]+=p2*vv.z; num[2][3]+=p2*vv.w;
            num[3][0]+=p3*vv.x; num[3][1]+=p3*vv.y; num[3][2]+=p3*vv.z; num[3][3]+=p3*vv.w;
        }
        __syncthreads();
    }
    // den: reduce across tx (16 lanes per half-warp), then 1 atomic
    #pragma unroll
    for (int i = 0; i < 4; i++){
        float d = den[i];
        #pragma unroll
        for (int o = 8; o > 0; o >>= 1) d += __shfl_down_sync(0xffffffffu, d, o, 16);
        if (tx == 0) atomicAdd(&g_den[q0 + ty*4 + i], d);
    }
    // num: each thread owns distinct elements; SPLITS-way contention only
    #pragma unroll
    for (int i = 0; i < 4; i++)
        #pragma unroll
        for (int j = 0; j < 4; j++)
            atomicAdd(&g_num[(size_t)(q0 + ty*4 + i)*DC + tx*4 + j], num[i][j]);
}

// ---------------------------------------------------------------------------
// echo = num/max(den,eps); neg_dists = -||echo - class_reps||; BCE mean
// one block (32 threads) per query row
__global__ void loss_kernel(const float* __restrict__ labels,
                            const float* __restrict__ creps,
                            float* __restrict__ out){
    __shared__ float echo_s[DC];
    const int b = blockIdx.x, t = threadIdx.x;
    float inv = 1.f / fmaxf(g_den[b], 1e-12f);
    echo_s[t]      = g_num[(size_t)b*DC + t]      * inv;
    echo_s[t + 32] = g_num[(size_t)b*DC + t + 32] * inv;
    __syncwarp();
    float le = 0.f;
    if (t < NLAB){
        float ss = 0.f;
        #pragma unroll
        for (int d = 0; d < DC; d++){
            float df = echo_s[d] - creps[t*DC + d];
            ss += df*df;
        }
        float x = -sqrtf(ss);                 // neg dist (<= 0)
        out[1 + (size_t)b*NLAB + t] = x;
        float y = labels[(size_t)b*NLAB + t];
        // BCEWithLogits elem: log1p(exp(x)) - y*x   (valid for x<=0)
        le = log1pf(expf(x)) - y*x;
    }
    #pragma unroll
    for (int o = 16; o > 0; o >>= 1) le += __shfl_down_sync(0xffffffffu, le, o);
    if (t == 0) atomicAdd(out, le * (1.f/((float)BQ*(float)NLAB)));
}

// ---------------------------------------------------------------------------
extern "C" void kernel_launch(void* const* d_in, const int* in_sizes, int n_in,
                              void* d_out, int out_size){
    const float* features    = (const float*)d_in[0];
    const float* labels      = (const float*)d_in[1];
    const float* ex_features = (const float*)d_in[2];
    const float* ex_classes  = (const float*)d_in[3];
    const float* g_w         = (const float*)d_in[4];
    const float* class_reps  = (const float*)d_in[5];
    float* out = (float*)d_out;

    float *pQ, *pK;
    cudaGetSymbolAddress((void**)&pQ, g_Q);
    cudaGetSymbolAddress((void**)&pK, g_K);

    zero_kernel<<<1024, 256>>>(out);

    dim3 blk(16, 16);
    gemm_nt64<<<dim3(BQ/64,  DF/64), blk>>>(features,    g_w, pQ, BQ,  DF, DIN);
    gemm_nt64<<<dim3(NEX/64, DF/64), blk>>>(ex_features, g_w, pK, NEX, DF, DIN);
    l2norm_kernel<<<BQ,  64>>>(pQ);
    l2norm_kernel<<<NEX, 64>>>(pK);
    exrep_kernel<<<NEX, 64>>>(ex_classes, class_reps);
    attn_kernel<<<dim3(BQ/64, SPLITS), blk>>>();
    loss_kernel<<<BQ, 32>>>(labels, class_reps, out);
}